// round 4
// baseline (speedup 1.0000x reference)
#include <cuda_runtime.h>
#include <cuda_bf16.h>
#include <cstdint>

// ContrastiveLoss (NT-Xent): BATCH=4096, DIM=128, TEMP=0.5
// z = normalize(concat(p1,p2)) [8192,128]; sim = z z^T (symmetric)
// loss_r = -sim[r,partner]/T + log(sum_{c!=r} exp(sim[r,c]/T)); out = mean.
// Sim GEMM in bf16 tensor cores (fp32 accumulate), ldmatrix fragments,
// UPPER-TRIANGLE blocks only (each off-diag block yields row AND col partials).

#define NB    4096
#define TN    8192          // 2*NB
#define D     128
#define INVT  2.0f          // 1/TEMP
#define CB    64            // 128-wide column blocks (TN/128)

__device__ float          g_zn[TN * D];   // normalized z, fp32 (positives)
__device__ __nv_bfloat16  g_zb[TN * D];   // normalized z, bf16 (GEMM)
__device__ float          g_part[TN * CB];
__device__ float          g_lpart[1024];

__device__ __forceinline__ float wred(float v) {
#pragma unroll
    for (int o = 16; o > 0; o >>= 1) v += __shfl_xor_sync(0xFFFFFFFFu, v, o);
    return v;
}

// ---------------- Kernel 1: row L2-normalize (warp per row) ----------------
__global__ void knorm(const float* __restrict__ p1, const float* __restrict__ p2) {
    int r    = blockIdx.x * 8 + (threadIdx.x >> 5);
    int lane = threadIdx.x & 31;
    const float* src = (r < NB) ? (p1 + (size_t)r * D) : (p2 + (size_t)(r - NB) * D);
    float4 v = reinterpret_cast<const float4*>(src)[lane];
    float ss = v.x * v.x + v.y * v.y + v.z * v.z + v.w * v.w;
    ss = wred(ss);
    float inv = 1.0f / fmaxf(sqrtf(ss), 1e-12f);
    v.x *= inv; v.y *= inv; v.z *= inv; v.w *= inv;
    reinterpret_cast<float4*>(g_zn + (size_t)r * D)[lane] = v;
    __nv_bfloat162 h0 = __floats2bfloat162_rn(v.x, v.y);
    __nv_bfloat162 h1 = __floats2bfloat162_rn(v.z, v.w);
    __nv_bfloat162* dst = reinterpret_cast<__nv_bfloat162*>(g_zb + (size_t)r * D);
    dst[lane * 2 + 0] = h0;
    dst[lane * 2 + 1] = h1;
}

// ------- Kernel 2: 128x128 sim tile, upper triangle, fused exp+mask+partials -------
// 256 threads = 8 warps (warp_m 0..3 x warp_n 0..1): warp tile 32(m) x 64(n).
#define LDA 72   // padded smem stride in bf16 (144B: rows advance 4 banks)

__device__ __forceinline__ void ldsm4(uint32_t addr, uint32_t& r0, uint32_t& r1,
                                      uint32_t& r2, uint32_t& r3) {
    asm volatile("ldmatrix.sync.aligned.m8n8.x4.shared.b16 {%0,%1,%2,%3}, [%4];"
                 : "=r"(r0), "=r"(r1), "=r"(r2), "=r"(r3) : "r"(addr));
}

__global__ void __launch_bounds__(256) ksim() {
    const int br = blockIdx.y;
    const int bc = blockIdx.x;
    if (bc < br) return;               // upper triangle only

    __shared__ __nv_bfloat16 As[128 * LDA];
    __shared__ __nv_bfloat16 Bs[128 * LDA];

    const int tid    = threadIdx.x;
    const int wid    = tid >> 5;
    const int lane   = tid & 31;
    const int g      = lane >> 2;      // 0..7
    const int tc     = lane & 3;       // 0..3
    const int lrow   = lane & 7;
    const int lt     = lane >> 3;
    const int warp_m = wid & 3;
    const int warp_n = wid >> 2;
    const int r0     = br << 7;
    const int c0     = bc << 7;

    const uint32_t smA = (uint32_t)__cvta_generic_to_shared(As);
    const uint32_t smB = (uint32_t)__cvta_generic_to_shared(Bs);

    uint32_t aBase[2];
#pragma unroll
    for (int tm = 0; tm < 2; ++tm)
        aBase[tm] = smA + (((warp_m * 32 + tm * 16 + lrow + (lt & 1) * 8) * LDA)
                           + (lt >> 1) * 8) * 2;
    uint32_t bBase[4];
#pragma unroll
    for (int tp = 0; tp < 4; ++tp)
        bBase[tp] = smB + (((warp_n * 64 + tp * 16 + lrow + (lt >> 1) * 8) * LDA)
                           + (lt & 1) * 8) * 2;

    float c[2][8][4];
#pragma unroll
    for (int i = 0; i < 2; ++i)
#pragma unroll
        for (int j = 0; j < 8; ++j)
#pragma unroll
            for (int q = 0; q < 4; ++q) c[i][j][q] = 0.f;

#pragma unroll
    for (int kc = 0; kc < 2; ++kc) {
        if (kc) __syncthreads();
#pragma unroll
        for (int i = 0; i < 4; ++i) {
            int idx = tid + i * 256;
            int row = idx >> 3;
            int u4  = idx & 7;
            *reinterpret_cast<uint4*>(&As[row * LDA + u4 * 8]) =
                *reinterpret_cast<const uint4*>(&g_zb[(size_t)(r0 + row) * D + kc * 64 + u4 * 8]);
            *reinterpret_cast<uint4*>(&Bs[row * LDA + u4 * 8]) =
                *reinterpret_cast<const uint4*>(&g_zb[(size_t)(c0 + row) * D + kc * 64 + u4 * 8]);
        }
        __syncthreads();

#pragma unroll
        for (int ks = 0; ks < 4; ++ks) {
            const uint32_t kOff = ks * 16 * 2;
            uint32_t b0[8], b1[8];
#pragma unroll
            for (int tp = 0; tp < 4; ++tp)
                ldsm4(bBase[tp] + kOff, b0[tp * 2], b1[tp * 2], b0[tp * 2 + 1], b1[tp * 2 + 1]);
#pragma unroll
            for (int tm = 0; tm < 2; ++tm) {
                uint32_t a0, a1, a2, a3;
                ldsm4(aBase[tm] + kOff, a0, a1, a2, a3);
#pragma unroll
                for (int tn = 0; tn < 8; ++tn) {
                    asm volatile(
                        "mma.sync.aligned.m16n8k16.row.col.f32.bf16.bf16.f32 "
                        "{%0,%1,%2,%3}, {%4,%5,%6,%7}, {%8,%9}, {%0,%1,%2,%3};\n"
                        : "+f"(c[tm][tn][0]), "+f"(c[tm][tn][1]),
                          "+f"(c[tm][tn][2]), "+f"(c[tm][tn][3])
                        : "r"(a0), "r"(a1), "r"(a2), "r"(a3),
                          "r"(b0[tn]), "r"(b1[tn]));
                }
            }
        }
    }

    // ---- Epilogue: e = exp(2*sim); row partials (diag-masked) + col partials ----
    float rs[2][2] = {{0.f, 0.f}, {0.f, 0.f}};   // [tm][rh] rows
    float cs[16];                                 // [tn*2+j] cols (no mask; off-diag use)
#pragma unroll
    for (int i = 0; i < 16; ++i) cs[i] = 0.f;

#pragma unroll
    for (int tm = 0; tm < 2; ++tm) {
#pragma unroll
        for (int tn = 0; tn < 8; ++tn) {
            int gcb = c0 + warp_n * 64 + tn * 8 + tc * 2;
            int gr0 = r0 + warp_m * 32 + tm * 16 + g;
            float e00 = __expf(INVT * c[tm][tn][0]);
            float e01 = __expf(INVT * c[tm][tn][1]);
            float e10 = __expf(INVT * c[tm][tn][2]);
            float e11 = __expf(INVT * c[tm][tn][3]);
            rs[tm][0] += (gr0     != gcb    ) ? e00 : 0.f;
            rs[tm][0] += (gr0     != gcb + 1) ? e01 : 0.f;
            rs[tm][1] += (gr0 + 8 != gcb    ) ? e10 : 0.f;
            rs[tm][1] += (gr0 + 8 != gcb + 1) ? e11 : 0.f;
            cs[tn * 2 + 0] += e00 + e10;
            cs[tn * 2 + 1] += e01 + e11;
        }
    }
    // rows: quad reduce (lanes sharing a row differ only in tc)
#pragma unroll
    for (int tm = 0; tm < 2; ++tm)
#pragma unroll
        for (int rh = 0; rh < 2; ++rh) {
            float v = rs[tm][rh];
            v += __shfl_xor_sync(0xFFFFFFFFu, v, 1);
            v += __shfl_xor_sync(0xFFFFFFFFu, v, 2);
            rs[tm][rh] = v;
        }
    // cols: reduce over g (lanes sharing cols differ in g bits: xor 4,8,16)
#pragma unroll
    for (int i = 0; i < 16; ++i) {
        float v = cs[i];
        v += __shfl_xor_sync(0xFFFFFFFFu, v, 4);
        v += __shfl_xor_sync(0xFFFFFFFFu, v, 8);
        v += __shfl_xor_sync(0xFFFFFFFFu, v, 16);
        cs[i] = v;
    }

    __syncthreads();                       // all warps done reading As/Bs
    float* rowred = reinterpret_cast<float*>(As);          // [2][128]
    float* colred = rowred + 256;                          // [8][64]

    if (tc == 0) {
#pragma unroll
        for (int tm = 0; tm < 2; ++tm)
#pragma unroll
            for (int rh = 0; rh < 2; ++rh) {
                int rb = warp_m * 32 + tm * 16 + rh * 8 + g;
                rowred[warp_n * 128 + rb] = rs[tm][rh];
            }
    }
    if (g == 0) {                          // lanes 0..3 hold col totals
#pragma unroll
        for (int tn = 0; tn < 8; ++tn) {
#pragma unroll
            for (int j = 0; j < 2; ++j)
                colred[wid * 64 + tn * 8 + tc * 2 + j] = cs[tn * 2 + j];
        }
    }
    __syncthreads();

    if (tid < 128) {
        // row-side: rows r0..r0+127, slot bc
        float rv = rowred[tid] + rowred[128 + tid];
        g_part[(size_t)(r0 + tid) * CB + bc] = rv;
        // col-side: rows c0..c0+127, slot br (skip diagonal blocks)
        if (br != bc) {
            int strip = tid >> 6;          // warp_n of this column
            int ci    = tid & 63;
            float cv = colred[(strip * 4 + 0) * 64 + ci]
                     + colred[(strip * 4 + 1) * 64 + ci]
                     + colred[(strip * 4 + 2) * 64 + ci]
                     + colred[(strip * 4 + 3) * 64 + ci];
            g_part[(size_t)(c0 + tid) * CB + br] = cv;
        }
    }
}

// ------- Kernel 3: per-row loss = -2*pos + log(denom); block partials -------
__global__ void kloss() {
    int r    = blockIdx.x * 8 + (threadIdx.x >> 5);
    int lane = threadIdx.x & 31;
    float d = g_part[(size_t)r * CB + lane] + g_part[(size_t)r * CB + lane + 32];
    d = wred(d);

    int p = (r < NB) ? (r + NB) : (r - NB);
    float4 a = reinterpret_cast<const float4*>(g_zn + (size_t)r * D)[lane];
    float4 b = reinterpret_cast<const float4*>(g_zn + (size_t)p * D)[lane];
    float pos = a.x * b.x + a.y * b.y + a.z * b.z + a.w * b.w;
    pos = wred(pos);

    __shared__ float s[8];
    if (lane == 0) s[threadIdx.x >> 5] = -INVT * pos + logf(d);
    __syncthreads();
    if (threadIdx.x == 0) {
        float t = 0.f;
#pragma unroll
        for (int i = 0; i < 8; ++i) t += s[i];
        g_lpart[blockIdx.x] = t;
    }
}

// ---------------- Kernel 4: final 1024 -> 1 reduce, /(2N) ----------------
__global__ void kfinal(float* __restrict__ out) {
    __shared__ float s[32];
    int t = threadIdx.x;
    float v = g_lpart[t];
    v = wred(v);
    if ((t & 31) == 0) s[t >> 5] = v;
    __syncthreads();
    if (t < 32) {
        float x = s[t];
        x = wred(x);
        if (t == 0) out[0] = x / (float)TN;
    }
}

extern "C" void kernel_launch(void* const* d_in, const int* in_sizes, int n_in,
                              void* d_out, int out_size) {
    const float* p1 = (const float*)d_in[0];
    const float* p2 = (const float*)d_in[1];
    float* out = (float*)d_out;

    knorm<<<TN / 8, 256>>>(p1, p2);
    dim3 grid(TN / 128, TN / 128);     // upper triangle filtered in-kernel
    ksim<<<grid, 256>>>();
    kloss<<<TN / 8, 256>>>();
    kfinal<<<1, 1024>>>(out);
}

// round 5
// speedup vs baseline: 1.3344x; 1.3344x over previous
#include <cuda_runtime.h>
#include <cuda_bf16.h>
#include <cstdint>

// ContrastiveLoss (NT-Xent): BATCH=4096, DIM=128, TEMP=0.5
// z = normalize(concat(p1,p2)) [8192,128]; sim = z z^T (symmetric)
// loss_r = -sim[r,partner]/T + log(sum_{c!=r} exp(sim[r,c]/T)); out = mean.
// bf16 tensor cores, ldmatrix fragments, upper-triangle blocks only
// (each off-diagonal block yields BOTH row and column exp-partials).

#define NB    4096
#define TN    8192          // 2*NB
#define D     128
#define INVT  2.0f          // 1/TEMP
#define CB    64            // 128-wide column blocks (TN/128)
#define NT    64            // tiles per side
#define NBLK  (NT * (NT + 1) / 2)   // 2080 triangle blocks
#define LDA   136           // smem stride in bf16 (272B = +4 banks/row, 16B-mult)

__device__ float          g_zn[TN * D];   // normalized z, fp32 (positives)
__device__ __nv_bfloat16  g_zb[TN * D];   // normalized z, bf16 (GEMM)
__device__ float          g_part[TN * CB];
__device__ float          g_lpart[1024];
__device__ unsigned       g_cnt = 0;      // threadfence-reduction counter

__device__ __forceinline__ float wred(float v) {
#pragma unroll
    for (int o = 16; o > 0; o >>= 1) v += __shfl_xor_sync(0xFFFFFFFFu, v, o);
    return v;
}

// ---------------- Kernel 1: row L2-normalize (warp per row) ----------------
__global__ void knorm(const float* __restrict__ p1, const float* __restrict__ p2) {
    int r    = blockIdx.x * 8 + (threadIdx.x >> 5);
    int lane = threadIdx.x & 31;
    const float* src = (r < NB) ? (p1 + (size_t)r * D) : (p2 + (size_t)(r - NB) * D);
    float4 v = reinterpret_cast<const float4*>(src)[lane];
    float ss = v.x * v.x + v.y * v.y + v.z * v.z + v.w * v.w;
    ss = wred(ss);
    float inv = 1.0f / fmaxf(sqrtf(ss), 1e-12f);
    v.x *= inv; v.y *= inv; v.z *= inv; v.w *= inv;
    reinterpret_cast<float4*>(g_zn + (size_t)r * D)[lane] = v;
    __nv_bfloat162 h0 = __floats2bfloat162_rn(v.x, v.y);
    __nv_bfloat162 h1 = __floats2bfloat162_rn(v.z, v.w);
    __nv_bfloat162* dst = reinterpret_cast<__nv_bfloat162*>(g_zb + (size_t)r * D);
    dst[lane * 2 + 0] = h0;
    dst[lane * 2 + 1] = h1;
}

// ------- Kernel 2: 128x128 sim tile, triangle grid, fused exp+mask+partials -------
// 256 threads = 8 warps (warp_m 0..3 x warp_n 0..1): warp tile 32(m) x 64(n).
__device__ __forceinline__ void ldsm4(uint32_t addr, uint32_t& r0, uint32_t& r1,
                                      uint32_t& r2, uint32_t& r3) {
    asm volatile("ldmatrix.sync.aligned.m8n8.x4.shared.b16 {%0,%1,%2,%3}, [%4];"
                 : "=r"(r0), "=r"(r1), "=r"(r2), "=r"(r3) : "r"(addr));
}

__global__ void __launch_bounds__(256) ksim() {
    // Decode linear triangle index -> (br, bc), br <= bc
    int b = blockIdx.x;
    int br = 0, rem = b;
    while (rem >= NT - br) { rem -= NT - br; ++br; }
    const int bc = br + rem;

    extern __shared__ __nv_bfloat16 sm[];
    __nv_bfloat16* As = sm;                 // [128][LDA]
    __nv_bfloat16* Bs = sm + 128 * LDA;     // [128][LDA]

    const int tid    = threadIdx.x;
    const int wid    = tid >> 5;
    const int lane   = tid & 31;
    const int g      = lane >> 2;      // 0..7
    const int tc     = lane & 3;       // 0..3
    const int lrow   = lane & 7;
    const int lt     = lane >> 3;
    const int warp_m = wid & 3;
    const int warp_n = wid >> 2;
    const int r0     = br << 7;
    const int c0     = bc << 7;

    // Load full 128x128 bf16 tiles (8 uint4 per thread per tile)
#pragma unroll
    for (int i = 0; i < 8; ++i) {
        int idx = tid + i * 256;           // 0..2047
        int row = idx >> 4;
        int u4  = idx & 15;
        *reinterpret_cast<uint4*>(&As[row * LDA + u4 * 8]) =
            *reinterpret_cast<const uint4*>(&g_zb[(size_t)(r0 + row) * D + u4 * 8]);
        *reinterpret_cast<uint4*>(&Bs[row * LDA + u4 * 8]) =
            *reinterpret_cast<const uint4*>(&g_zb[(size_t)(c0 + row) * D + u4 * 8]);
    }

    const uint32_t smA = (uint32_t)__cvta_generic_to_shared(As);
    const uint32_t smB = (uint32_t)__cvta_generic_to_shared(Bs);
    uint32_t aBase[2];
#pragma unroll
    for (int tm = 0; tm < 2; ++tm)
        aBase[tm] = smA + (((warp_m * 32 + tm * 16 + lrow + (lt & 1) * 8) * LDA)
                           + (lt >> 1) * 8) * 2;
    uint32_t bBase[4];
#pragma unroll
    for (int tp = 0; tp < 4; ++tp)
        bBase[tp] = smB + (((warp_n * 64 + tp * 16 + lrow + (lt >> 1) * 8) * LDA)
                           + (lt & 1) * 8) * 2;

    float c[2][8][4];
#pragma unroll
    for (int i = 0; i < 2; ++i)
#pragma unroll
        for (int j = 0; j < 8; ++j)
#pragma unroll
            for (int q = 0; q < 4; ++q) c[i][j][q] = 0.f;

    __syncthreads();

#pragma unroll
    for (int ks = 0; ks < 8; ++ks) {
        const uint32_t kOff = ks * 16 * 2;
        uint32_t b0[8], b1[8];
#pragma unroll
        for (int tp = 0; tp < 4; ++tp)
            ldsm4(bBase[tp] + kOff, b0[tp * 2], b1[tp * 2], b0[tp * 2 + 1], b1[tp * 2 + 1]);
#pragma unroll
        for (int tm = 0; tm < 2; ++tm) {
            uint32_t a0, a1, a2, a3;
            ldsm4(aBase[tm] + kOff, a0, a1, a2, a3);
#pragma unroll
            for (int tn = 0; tn < 8; ++tn) {
                asm volatile(
                    "mma.sync.aligned.m16n8k16.row.col.f32.bf16.bf16.f32 "
                    "{%0,%1,%2,%3}, {%4,%5,%6,%7}, {%8,%9}, {%0,%1,%2,%3};\n"
                    : "+f"(c[tm][tn][0]), "+f"(c[tm][tn][1]),
                      "+f"(c[tm][tn][2]), "+f"(c[tm][tn][3])
                    : "r"(a0), "r"(a1), "r"(a2), "r"(a3),
                      "r"(b0[tn]), "r"(b1[tn]));
            }
        }
    }

    // ---- Epilogue: e = exp(2*sim); row partials (diag-masked) + col partials ----
    float rs[2][2] = {{0.f, 0.f}, {0.f, 0.f}};
    float cs[16];
#pragma unroll
    for (int i = 0; i < 16; ++i) cs[i] = 0.f;

#pragma unroll
    for (int tm = 0; tm < 2; ++tm) {
#pragma unroll
        for (int tn = 0; tn < 8; ++tn) {
            int gcb = c0 + warp_n * 64 + tn * 8 + tc * 2;
            int gr0 = r0 + warp_m * 32 + tm * 16 + g;
            float e00 = __expf(INVT * c[tm][tn][0]);
            float e01 = __expf(INVT * c[tm][tn][1]);
            float e10 = __expf(INVT * c[tm][tn][2]);
            float e11 = __expf(INVT * c[tm][tn][3]);
            rs[tm][0] += (gr0     != gcb    ) ? e00 : 0.f;
            rs[tm][0] += (gr0     != gcb + 1) ? e01 : 0.f;
            rs[tm][1] += (gr0 + 8 != gcb    ) ? e10 : 0.f;
            rs[tm][1] += (gr0 + 8 != gcb + 1) ? e11 : 0.f;
            cs[tn * 2 + 0] += e00 + e10;
            cs[tn * 2 + 1] += e01 + e11;
        }
    }
#pragma unroll
    for (int tm = 0; tm < 2; ++tm)
#pragma unroll
        for (int rh = 0; rh < 2; ++rh) {
            float v = rs[tm][rh];
            v += __shfl_xor_sync(0xFFFFFFFFu, v, 1);
            v += __shfl_xor_sync(0xFFFFFFFFu, v, 2);
            rs[tm][rh] = v;
        }
#pragma unroll
    for (int i = 0; i < 16; ++i) {
        float v = cs[i];
        v += __shfl_xor_sync(0xFFFFFFFFu, v, 4);
        v += __shfl_xor_sync(0xFFFFFFFFu, v, 8);
        v += __shfl_xor_sync(0xFFFFFFFFu, v, 16);
        cs[i] = v;
    }

    __syncthreads();                       // done reading As/Bs
    float* rowred = reinterpret_cast<float*>(sm);          // [2][128]
    float* colred = rowred + 256;                          // [8][64]

    if (tc == 0) {
#pragma unroll
        for (int tm = 0; tm < 2; ++tm)
#pragma unroll
            for (int rh = 0; rh < 2; ++rh) {
                int rb = warp_m * 32 + tm * 16 + rh * 8 + g;
                rowred[warp_n * 128 + rb] = rs[tm][rh];
            }
    }
    if (g == 0) {
#pragma unroll
        for (int tn = 0; tn < 8; ++tn)
#pragma unroll
            for (int j = 0; j < 2; ++j)
                colred[wid * 64 + tn * 8 + tc * 2 + j] = cs[tn * 2 + j];
    }
    __syncthreads();

    if (tid < 128) {
        float rv = rowred[tid] + rowred[128 + tid];
        g_part[(size_t)(r0 + tid) * CB + bc] = rv;
        if (br != bc) {
            int strip = tid >> 6;
            int ci    = tid & 63;
            float cv = colred[(strip * 4 + 0) * 64 + ci]
                     + colred[(strip * 4 + 1) * 64 + ci]
                     + colred[(strip * 4 + 2) * 64 + ci]
                     + colred[(strip * 4 + 3) * 64 + ci];
            g_part[(size_t)(c0 + tid) * CB + br] = cv;
        }
    }
}

// ------- Kernel 3: per-row loss; last block reduces all partials -> out -------
__global__ void kloss(float* __restrict__ out) {
    int r    = blockIdx.x * 8 + (threadIdx.x >> 5);
    int lane = threadIdx.x & 31;
    float d = g_part[(size_t)r * CB + lane] + g_part[(size_t)r * CB + lane + 32];
    d = wred(d);

    int p = (r < NB) ? (r + NB) : (r - NB);
    float4 a = reinterpret_cast<const float4*>(g_zn + (size_t)r * D)[lane];
    float4 b = reinterpret_cast<const float4*>(g_zn + (size_t)p * D)[lane];
    float pos = a.x * b.x + a.y * b.y + a.z * b.z + a.w * b.w;
    pos = wred(pos);

    __shared__ float s[8];
    __shared__ bool  last;
    if (lane == 0) s[threadIdx.x >> 5] = -INVT * pos + logf(d);
    __syncthreads();
    if (threadIdx.x == 0) {
        float t = 0.f;
#pragma unroll
        for (int i = 0; i < 8; ++i) t += s[i];
        g_lpart[blockIdx.x] = t;
        __threadfence();
        unsigned old = atomicAdd(&g_cnt, 1u);
        last = (old == gridDim.x - 1);
    }
    __syncthreads();

    if (last) {                            // final 1024 -> 1, fixed order
        __threadfence();
        int t4 = threadIdx.x;              // 256 threads x 4 values
        float v = g_lpart[t4] + g_lpart[t4 + 256] + g_lpart[t4 + 512] + g_lpart[t4 + 768];
        v = wred(v);
        __shared__ float fs[8];
        if ((t4 & 31) == 0) fs[t4 >> 5] = v;
        __syncthreads();
        if (t4 == 0) {
            float x = 0.f;
#pragma unroll
            for (int i = 0; i < 8; ++i) x += fs[i];
            out[0] = x / (float)TN;
            g_cnt = 0;                     // reset for next graph replay
        }
    }
}

extern "C" void kernel_launch(void* const* d_in, const int* in_sizes, int n_in,
                              void* d_out, int out_size) {
    const float* p1 = (const float*)d_in[0];
    const float* p2 = (const float*)d_in[1];
    float* out = (float*)d_out;

    knorm<<<TN / 8, 256>>>(p1, p2);
    static bool attr_set = false;
    if (!attr_set) {
        cudaFuncSetAttribute(ksim, cudaFuncAttributeMaxDynamicSharedMemorySize,
                             2 * 128 * LDA * (int)sizeof(__nv_bfloat16));
        attr_set = true;
    }
    ksim<<<NBLK, 256, 2 * 128 * LDA * sizeof(__nv_bfloat16)>>>();
    kloss<<<TN / 8, 256>>>(out);
}

// round 9
// speedup vs baseline: 1.3387x; 1.0032x over previous
#include <cuda_runtime.h>
#include <cuda_bf16.h>
#include <cuda_fp8.h>
#include <cstdint>

// ContrastiveLoss (NT-Xent): BATCH=4096, DIM=128, TEMP=0.5
// z = normalize(concat(p1,p2)) [8192,128]; sim = z z^T (symmetric)
// loss_r = -sim[r,partner]/T + log(sum_{c!=r} exp(sim[r,c]/T)); out = mean.
// Sim GEMM in FP8 e4m3 tensor cores (z scaled x16, fp32 accumulate, scale
// folded into exp), upper-triangle blocks only (row AND col partials per block).
// Positive-pair dots in fp32. Tile loads via cp.async.cg.

#define NB    4096
#define TN    8192          // 2*NB
#define D     128
#define CB    64            // 128-wide column blocks (TN/128)
#define NT    64            // tiles per side
#define NBLK  (NT * (NT + 1) / 2)   // 2080 triangle blocks
#define LDB   144           // smem tile stride in BYTES (128 + 16 pad)
#define EXS   0.0078125f    // (1/TEMP) / (16*16): exp scale on raw fp8 accum
#define INVT  2.0f

__device__ float    g_zn[TN * D];        // normalized z, fp32 (positives)
__device__ uint32_t g_z8[TN * D / 4];    // normalized z * 16, e4m3 (GEMM)
__device__ float    g_part[TN * CB];
__device__ float    g_lpart[1024];
__device__ unsigned g_cnt = 0;

__device__ __forceinline__ float wred(float v) {
#pragma unroll
    for (int o = 16; o > 0; o >>= 1) v += __shfl_xor_sync(0xFFFFFFFFu, v, o);
    return v;
}

__device__ __forceinline__ uint32_t pack_e4m3x4(float x, float y, float z, float w) {
    uint16_t lo, hi;
    asm("cvt.rn.satfinite.e4m3x2.f32 %0, %1, %2;" : "=h"(lo) : "f"(y), "f"(x));
    asm("cvt.rn.satfinite.e4m3x2.f32 %0, %1, %2;" : "=h"(hi) : "f"(w), "f"(z));
    return (uint32_t)lo | ((uint32_t)hi << 16);
}

__device__ __forceinline__ void cpasync16(uint32_t smem_dst, const void* gsrc) {
    asm volatile("cp.async.cg.shared.global [%0], [%1], 16;"
                 :: "r"(smem_dst), "l"(gsrc));
}

// ------------- Kernel 1: L2-normalize, 2 rows per warp (MLP=2) -------------
__global__ void knorm(const float* __restrict__ p1, const float* __restrict__ p2) {
    int wid  = threadIdx.x >> 5;
    int lane = threadIdx.x & 31;
    int r0   = blockIdx.x * 16 + wid * 2;

#pragma unroll
    for (int j = 0; j < 2; ++j) {
        int r = r0 + j;
        const float* src = (r < NB) ? (p1 + (size_t)r * D) : (p2 + (size_t)(r - NB) * D);
        float4 v = reinterpret_cast<const float4*>(src)[lane];
        float ss = v.x * v.x + v.y * v.y + v.z * v.z + v.w * v.w;
        ss = wred(ss);
        float inv = 1.0f / fmaxf(sqrtf(ss), 1e-12f);
        v.x *= inv; v.y *= inv; v.z *= inv; v.w *= inv;
        reinterpret_cast<float4*>(g_zn + (size_t)r * D)[lane] = v;
        g_z8[(size_t)r * (D / 4) + lane] =
            pack_e4m3x4(v.x * 16.f, v.y * 16.f, v.z * 16.f, v.w * 16.f);
    }
}

// ---- Kernel 2: 128x128 sim tile, FP8 mma, triangle grid, fused epilogue ----
// 256 threads = 8 warps (warp_m 0..3 x warp_n 0..1): warp tile 32(m) x 64(n).
__device__ __forceinline__ void ldsm4(uint32_t addr, uint32_t& r0, uint32_t& r1,
                                      uint32_t& r2, uint32_t& r3) {
    asm volatile("ldmatrix.sync.aligned.m8n8.x4.shared.b16 {%0,%1,%2,%3}, [%4];"
                 : "=r"(r0), "=r"(r1), "=r"(r2), "=r"(r3) : "r"(addr));
}

__global__ void __launch_bounds__(256, 2) ksim() {
    int b = blockIdx.x;
    int br = 0, rem = b;
    while (rem >= NT - br) { rem -= NT - br; ++br; }
    const int bc = br + rem;

    __shared__ uint8_t As[128 * LDB];     // 18 KB
    __shared__ uint8_t Bs[128 * LDB];     // 18 KB

    const int tid    = threadIdx.x;
    const int wid    = tid >> 5;
    const int lane   = tid & 31;
    const int g      = lane >> 2;
    const int tc     = lane & 3;
    const int lrow   = lane & 7;
    const int lt     = lane >> 3;
    const int warp_m = wid & 3;
    const int warp_n = wid >> 2;
    const int r0     = br << 7;
    const int c0     = bc << 7;

    const uint32_t smA = (uint32_t)__cvta_generic_to_shared(As);
    const uint32_t smB = (uint32_t)__cvta_generic_to_shared(Bs);

    // Async-load 128x128 fp8 tiles: 4 x 16B per thread per tile
#pragma unroll
    for (int i = 0; i < 4; ++i) {
        int idx = tid + i * 256;          // 0..1023
        int row = idx >> 3;
        int u4  = idx & 7;                // 16B chunk
        cpasync16(smA + row * LDB + u4 * 16,
                  reinterpret_cast<const uint4*>(&g_z8[(size_t)(r0 + row) * (D / 4)]) + u4);
        cpasync16(smB + row * LDB + u4 * 16,
                  reinterpret_cast<const uint4*>(&g_z8[(size_t)(c0 + row) * (D / 4)]) + u4);
    }
    asm volatile("cp.async.commit_group;");

    // A ldsm tiles (per tm): t0=(r,k0) t1=(r+8,k0) t2=(r,k16) t3=(r+8,k16)
    uint32_t aBase[2];
#pragma unroll
    for (int tm = 0; tm < 2; ++tm)
        aBase[tm] = smA + (warp_m * 32 + tm * 16 + lrow + (lt & 1) * 8) * LDB
                        + (lt >> 1) * 16;
    // B ldsm tiles (per tp): t0=(n,k0) t1=(n,k16) t2=(n+8,k0) t3=(n+8,k16)
    uint32_t bBase[4];
#pragma unroll
    for (int tp = 0; tp < 4; ++tp)
        bBase[tp] = smB + (warp_n * 64 + tp * 16 + lrow + (lt >> 1) * 8) * LDB
                        + (lt & 1) * 16;

    float c[2][8][4];
#pragma unroll
    for (int i = 0; i < 2; ++i)
#pragma unroll
        for (int j = 0; j < 8; ++j)
#pragma unroll
            for (int q = 0; q < 4; ++q) c[i][j][q] = 0.f;

    asm volatile("cp.async.wait_group 0;");
    __syncthreads();

#pragma unroll
    for (int ks = 0; ks < 4; ++ks) {       // K=128, 32 per mma
        const uint32_t kOff = ks * 32;     // bytes
        uint32_t b0[8], b1[8];
#pragma unroll
        for (int tp = 0; tp < 4; ++tp)
            ldsm4(bBase[tp] + kOff, b0[tp * 2], b1[tp * 2], b0[tp * 2 + 1], b1[tp * 2 + 1]);
#pragma unroll
        for (int tm = 0; tm < 2; ++tm) {
            uint32_t a0, a1, a2, a3;
            ldsm4(aBase[tm] + kOff, a0, a1, a2, a3);
#pragma unroll
            for (int tn = 0; tn < 8; ++tn) {
                asm volatile(
                    "mma.sync.aligned.m16n8k32.row.col.f32.e4m3.e4m3.f32 "
                    "{%0,%1,%2,%3}, {%4,%5,%6,%7}, {%8,%9}, {%0,%1,%2,%3};\n"
                    : "+f"(c[tm][tn][0]), "+f"(c[tm][tn][1]),
                      "+f"(c[tm][tn][2]), "+f"(c[tm][tn][3])
                    : "r"(a0), "r"(a1), "r"(a2), "r"(a3),
                      "r"(b0[tn]), "r"(b1[tn]));
            }
        }
    }

    // ---- Epilogue: e = exp(EXS*acc); row partials (diag-masked) + col partials ----
    float rs[2][2] = {{0.f, 0.f}, {0.f, 0.f}};
    float cs[16];
#pragma unroll
    for (int i = 0; i < 16; ++i) cs[i] = 0.f;

#pragma unroll
    for (int tm = 0; tm < 2; ++tm) {
#pragma unroll
        for (int tn = 0; tn < 8; ++tn) {
            int gcb = c0 + warp_n * 64 + tn * 8 + tc * 2;
            int gr0 = r0 + warp_m * 32 + tm * 16 + g;
            float e00 = __expf(EXS * c[tm][tn][0]);
            float e01 = __expf(EXS * c[tm][tn][1]);
            float e10 = __expf(EXS * c[tm][tn][2]);
            float e11 = __expf(EXS * c[tm][tn][3]);
            rs[tm][0] += (gr0     != gcb    ) ? e00 : 0.f;
            rs[tm][0] += (gr0     != gcb + 1) ? e01 : 0.f;
            rs[tm][1] += (gr0 + 8 != gcb    ) ? e10 : 0.f;
            rs[tm][1] += (gr0 + 8 != gcb + 1) ? e11 : 0.f;
            cs[tn * 2 + 0] += e00 + e10;
            cs[tn * 2 + 1] += e01 + e11;
        }
    }
#pragma unroll
    for (int tm = 0; tm < 2; ++tm)
#pragma unroll
        for (int rh = 0; rh < 2; ++rh) {
            float v = rs[tm][rh];
            v += __shfl_xor_sync(0xFFFFFFFFu, v, 1);
            v += __shfl_xor_sync(0xFFFFFFFFu, v, 2);
            rs[tm][rh] = v;
        }
#pragma unroll
    for (int i = 0; i < 16; ++i) {
        float v = cs[i];
        v += __shfl_xor_sync(0xFFFFFFFFu, v, 4);
        v += __shfl_xor_sync(0xFFFFFFFFu, v, 8);
        v += __shfl_xor_sync(0xFFFFFFFFu, v, 16);
        cs[i] = v;
    }

    __syncthreads();                        // done reading As/Bs
    float* rowred = reinterpret_cast<float*>(As);   // [2][128]
    float* colred = rowred + 256;                   // [8][64]

    if (tc == 0) {
#pragma unroll
        for (int tm = 0; tm < 2; ++tm)
#pragma unroll
            for (int rh = 0; rh < 2; ++rh) {
                int rb = warp_m * 32 + tm * 16 + rh * 8 + g;
                rowred[warp_n * 128 + rb] = rs[tm][rh];
            }
    }
    if (g == 0) {
#pragma unroll
        for (int tn = 0; tn < 8; ++tn)
#pragma unroll
            for (int j = 0; j < 2; ++j)
                colred[wid * 64 + tn * 8 + tc * 2 + j] = cs[tn * 2 + j];
    }
    __syncthreads();

    if (tid < 128) {
        float rv = rowred[tid] + rowred[128 + tid];
        g_part[(size_t)(r0 + tid) * CB + bc] = rv;
        if (br != bc) {
            int strip = tid >> 6;
            int ci    = tid & 63;
            float cv = colred[(strip * 4 + 0) * 64 + ci]
                     + colred[(strip * 4 + 1) * 64 + ci]
                     + colred[(strip * 4 + 2) * 64 + ci]
                     + colred[(strip * 4 + 3) * 64 + ci];
            g_part[(size_t)(c0 + tid) * CB + br] = cv;
        }
    }
}

// ------- Kernel 3: per-row loss; last block reduces all partials -> out -------
__global__ void kloss(float* __restrict__ out) {
    int r    = blockIdx.x * 8 + (threadIdx.x >> 5);
    int lane = threadIdx.x & 31;
    float d = g_part[(size_t)r * CB + lane] + g_part[(size_t)r * CB + lane + 32];
    d = wred(d);

    int p = (r < NB) ? (r + NB) : (r - NB);
    float4 a = reinterpret_cast<const float4*>(g_zn + (size_t)r * D)[lane];
    float4 b = reinterpret_cast<const float4*>(g_zn + (size_t)p * D)[lane];
    float pos = a.x * b.x + a.y * b.y + a.z * b.z + a.w * b.w;
    pos = wred(pos);

    __shared__ float s[8];
    __shared__ bool  last;
    if (lane == 0) s[threadIdx.x >> 5] = -INVT * pos + logf(d);
    __syncthreads();
    if (threadIdx.x == 0) {
        float t = 0.f;
#pragma unroll
        for (int i = 0; i < 8; ++i) t += s[i];
        g_lpart[blockIdx.x] = t;
        __threadfence();
        unsigned old = atomicAdd(&g_cnt, 1u);
        last = (old == gridDim.x - 1);
    }
    __syncthreads();

    if (last) {
        __threadfence();
        int t4 = threadIdx.x;
        float v = g_lpart[t4] + g_lpart[t4 + 256] + g_lpart[t4 + 512] + g_lpart[t4 + 768];
        v = wred(v);
        __shared__ float fs[8];
        if ((t4 & 31) == 0) fs[t4 >> 5] = v;
        __syncthreads();
        if (t4 == 0) {
            float x = 0.f;
#pragma unroll
            for (int i = 0; i < 8; ++i) x += fs[i];
            out[0] = x / (float)TN;
            g_cnt = 0;
        }
    }
}

extern "C" void kernel_launch(void* const* d_in, const int* in_sizes, int n_in,
                              void* d_out, int out_size) {
    const float* p1 = (const float*)d_in[0];
    const float* p2 = (const float*)d_in[1];
    float* out = (float*)d_out;

    knorm<<<TN / 16, 256>>>(p1, p2);
    ksim<<<NBLK, 256>>>();
    kloss<<<TN / 8, 256>>>(out);
}